// round 14
// baseline (speedup 1.0000x reference)
#include <cuda_runtime.h>
#include <cuda_bf16.h>
#include <math.h>
#include <stdint.h>

// Problem constants (fixed by the reference)
#define BB 64
#define TT 512
#define FF 513
#define HH 50
#define G4 200          // 4*H
#define MROWS (BB*TT)   // 32768

#define KP1 544         // K=513 padded to 17*32
#define NKC1 17
#define KP2 64          // K=50 padded to 2*32
#define NKC2 2
#define NP1 256         // W_ih rows padded
#define NP2 512         // W_out rows 0..511 (col 512 via gemv)
#define XGS 256         // xg row stride (padded for aligned float4 stores)

// Scratch (static device globals — no allocation in kernel_launch)
__device__ float g_xg[MROWS * XGS];
__device__ __nv_bfloat16 g_wihhi[NP1 * KP1];
__device__ __nv_bfloat16 g_wihlo[NP1 * KP1];
__device__ __nv_bfloat16 g_hshi[MROWS * KP2];
__device__ __nv_bfloat16 g_hslo[MROWS * KP2];
__device__ __nv_bfloat16 g_wohi[NP2 * KP2];
__device__ __nv_bfloat16 g_wolo[NP2 * KP2];

// ===========================================================================
// PTX helpers
// ===========================================================================
__device__ __forceinline__ uint32_t smem_u32(const void* p) {
    uint32_t a;
    asm("{ .reg .u64 t; cvta.to.shared.u64 t, %1; cvt.u32.u64 %0, t; }"
        : "=r"(a) : "l"(p));
    return a;
}
__device__ __forceinline__ void ldsm4(uint32_t* r, uint32_t a) {
    asm volatile("ldmatrix.sync.aligned.m8n8.x4.shared.b16 {%0,%1,%2,%3}, [%4];"
                 : "=r"(r[0]), "=r"(r[1]), "=r"(r[2]), "=r"(r[3]) : "r"(a));
}
__device__ __forceinline__ void mma16816(float* c, const uint32_t* a,
                                         const uint32_t* b) {
    asm volatile(
        "mma.sync.aligned.m16n8k16.row.col.f32.bf16.bf16.f32 "
        "{%0,%1,%2,%3}, {%4,%5,%6,%7}, {%8,%9}, {%0,%1,%2,%3};"
        : "+f"(c[0]), "+f"(c[1]), "+f"(c[2]), "+f"(c[3])
        : "r"(a[0]), "r"(a[1]), "r"(a[2]), "r"(a[3]), "r"(b[0]), "r"(b[1]));
}
__device__ __forceinline__ void cpasync16(uint32_t dst, const void* src) {
    asm volatile("cp.async.cg.shared.global [%0], [%1], 16;"
                 :: "r"(dst), "l"(src));
}
__device__ __forceinline__ void cpasync4_zfill(uint32_t dst, const void* src,
                                               int srcsz) {
    asm volatile("cp.async.ca.shared.global [%0], [%1], 4, %2;"
                 :: "r"(dst), "l"(src), "r"(srcsz));
}
#define CP_COMMIT() asm volatile("cp.async.commit_group;" ::: "memory")
#define CP_WAIT0()  asm volatile("cp.async.wait_group 0;" ::: "memory")

// fast activations: single MUFU.EX2-based, clamped; rel err ~1e-6
__device__ __forceinline__ float sigm_fast(float x) {
    x = fminf(fmaxf(x, -30.f), 30.f);
    return __fdividef(1.f, 1.f + __expf(-x));
}
__device__ __forceinline__ float tanh_fast(float x) {
    x = fminf(fmaxf(x, -15.f), 15.f);
    float e = __expf(-2.f * x);
    return __fdividef(1.f - e, 1.f + e);
}

// ===========================================================================
// Weight conversion: fp32 -> zero-padded bf16 hi/lo (W_ih, W_out only).
// ===========================================================================
#define NB_WIH ((NP1 * (KP1/8) + 255) / 256)        // 68
#define NB_WO  ((NP2 * (KP2/8) + 255) / 256)        // 16

__device__ __forceinline__ void conv_body(
    const float* __restrict__ src, __nv_bfloat16* __restrict__ hi,
    __nv_bfloat16* __restrict__ lo, int srcR, int srcC, int dstR, int dstC,
    int idx)
{
    int gpr = dstC >> 3;
    if (idx >= dstR * gpr) return;
    int r = idx / gpr;
    int c0 = (idx - r * gpr) * 8;
    __nv_bfloat16 hv[8], lv[8];
#pragma unroll
    for (int i = 0; i < 8; ++i) {
        int c = c0 + i;
        float v = (r < srcR && c < srcC) ? __ldg(&src[(size_t)r * srcC + c]) : 0.f;
        hv[i] = __float2bfloat16(v);
        lv[i] = __float2bfloat16(v - __bfloat162float(hv[i]));
    }
    *(uint4*)&hi[(size_t)r * dstC + c0] = *(uint4*)hv;
    *(uint4*)&lo[(size_t)r * dstC + c0] = *(uint4*)lv;
}

__global__ void conv_w(const float* __restrict__ wih,
                       const float* __restrict__ wo)
{
    int gb = blockIdx.x;
    if (gb < NB_WIH)
        conv_body(wih, g_wihhi, g_wihlo, G4, FF, NP1, KP1,
                  gb * 256 + threadIdx.x);
    else
        conv_body(wo, g_wohi, g_wolo, FF, HH, NP2, KP2,
                  (gb - NB_WIH) * 256 + threadIdx.x);
}

// ===========================================================================
// Shared GEMM building blocks
// ===========================================================================
#define LDR80 80
#define ABF_BYTES 10240                  // 128 rows x 80 B (bf16 tile)

// ---------------------------------------------------------------------------
// FUSED GEMM1: xg[m, 0:200] = x[m,:] @ W_ih^T + b_ih, fp32 x converted
// to bf16 hi/lo IN-KERNEL (smem staging). Block 128x128, KC=32.
// Grid (2, 256): n-tile fastest -> A re-read hits L2.
// ---------------------------------------------------------------------------
#define RAW_OFF   0
#define RAW_ROWB  144                    // 32 fp32 (128 B) + 16 B pad
#define RAW_BYTES (128 * RAW_ROWB)       // 18432
#define CONVA_OFF RAW_BYTES              // 18432
#define CONVA_ST  (2 * ABF_BYTES)        // 20480 per stage (hi|lo)
#define B1_OFF    (CONVA_OFF + 2 * CONVA_ST)   // 59392
#define B1_ST     (2 * ABF_BYTES)
#define BIAS1_OFF (B1_OFF + 2 * B1_ST)   // 100352
#define SMEM1_TOTAL (BIAS1_OFF + 512)    // 100864

__global__ __launch_bounds__(256, 2) void gemm1_fused(
    const float* __restrict__ x,
    const __nv_bfloat16* __restrict__ Bhi, const __nv_bfloat16* __restrict__ Blo,
    const float* __restrict__ bias, float* __restrict__ C)
{
    extern __shared__ __align__(16) char smem[];
    const uint32_t sbase = smem_u32(smem);
    float* bias_s = (float*)(smem + BIAS1_OFF);

    const int tid  = threadIdx.x;
    const int lane = tid & 31;
    const int wid  = tid >> 5;
    const int wm   = wid & 1;
    const int wn   = wid >> 1;

    const int n0 = blockIdx.x * 128;   // n fastest
    const int m0 = blockIdx.y * 128;

    bool nj_act[4], jj_act[2];
#pragma unroll
    for (int nj = 0; nj < 4; ++nj)
        nj_act[nj] = (n0 + wn * 32 + nj * 8) < G4;
    jj_act[0] = nj_act[0] | nj_act[1];
    jj_act[1] = nj_act[2] | nj_act[3];
    const bool warp_act = jj_act[0] | jj_act[1];

    float acc[4][4][4];
#pragma unroll
    for (int i = 0; i < 4; ++i)
#pragma unroll
        for (int j = 0; j < 4; ++j)
#pragma unroll
            for (int q = 0; q < 4; ++q) acc[i][j][q] = 0.f;

    // raw fp32 A chunk: 128 x 32 fp32, 4-byte zfill cp.async (row stride 513)
    auto issueA = [&](int kc) {
#pragma unroll
        for (int i = 0; i < 16; ++i) {
            const int w = tid + i * 256;       // 0..4095
            const int row = w >> 5;
            const int col = w & 31;
            const int gc = kc * 32 + col;
            const uint32_t dst = sbase + RAW_OFF + row * RAW_ROWB + col * 4;
            const float* src = x + (size_t)(m0 + row) * FF + gc;
            cpasync4_zfill(dst, src, (gc < FF) ? 4 : 0);
        }
    };
    // B chunk (pre-converted bf16 hi/lo, Kp1 stride)
    auto issueB = [&](int kc, int stage) {
        const uint32_t s32 = sbase + B1_OFF + stage * B1_ST;
#pragma unroll
        for (int i = 0; i < 2; ++i) {
            const int chunk = tid + i * 256;   // 0..511
            const int row = chunk >> 2;
            const int g = chunk & 3;
            const uint32_t dofs = row * LDR80 + g * 16;
            const size_t bofs = (size_t)(n0 + row) * KP1 + kc * 32 + g * 8;
            cpasync16(s32 + dofs, Bhi + bofs);
            cpasync16(s32 + ABF_BYTES + dofs, Blo + bofs);
        }
    };

    issueA(0);
    issueB(0, 0);
    CP_COMMIT();
    if (tid < 128)
        bias_s[tid] = (n0 + tid < G4) ? bias[n0 + tid] : 0.f;

    const int crow  = tid >> 1;
    const int chalf = (tid & 1) << 4;   // 0 or 16

    for (int kc = 0; kc < NKC1; ++kc) {
        const int cur = kc & 1;
        CP_WAIT0();
        __syncthreads();   // raw A kc + B kc ready; prior compute done

        // ---- convert raw fp32 -> bf16 hi/lo into conv stage `cur`
        {
            const float4* rp =
                (const float4*)(smem + RAW_OFF + crow * RAW_ROWB + chalf * 4);
            float f[16];
#pragma unroll
            for (int i = 0; i < 4; ++i)
                *(float4*)&f[i * 4] = rp[i];
            __nv_bfloat16 hv[16], lv[16];
#pragma unroll
            for (int i = 0; i < 16; ++i) {
                hv[i] = __float2bfloat16(f[i]);
                lv[i] = __float2bfloat16(f[i] - __bfloat162float(hv[i]));
            }
            char* hd = smem + CONVA_OFF + cur * CONVA_ST + crow * LDR80 + chalf * 2;
            *(uint4*)hd        = ((uint4*)hv)[0];
            *(uint4*)(hd + 16) = ((uint4*)hv)[1];
            char* ld2 = hd + ABF_BYTES;
            *(uint4*)ld2        = ((uint4*)lv)[0];
            *(uint4*)(ld2 + 16) = ((uint4*)lv)[1];
        }
        __syncthreads();   // conversions visible; raw buffer free

        if (kc + 1 < NKC1) {
            issueA(kc + 1);
            issueB(kc + 1, cur ^ 1);
            CP_COMMIT();
        }

        const uint32_t sAhi = sbase + CONVA_OFF + cur * CONVA_ST;
        const uint32_t sAlo = sAhi + ABF_BYTES;
        const uint32_t sBhi = sbase + B1_OFF + cur * B1_ST;
        const uint32_t sBlo = sBhi + ABF_BYTES;

        if (warp_act) {
#pragma unroll
            for (int k16 = 0; k16 < 2; ++k16) {
                const uint32_t kb = k16 * 32;
                uint32_t ah[4][4], al[4][4];
#pragma unroll
                for (int mi = 0; mi < 4; ++mi) {
                    const uint32_t off =
                        (uint32_t)(wm * 64 + mi * 16 + (lane & 15)) * LDR80 +
                        ((lane >> 4) * 16) + kb;
                    ldsm4(ah[mi], sAhi + off);
                    ldsm4(al[mi], sAlo + off);
                }
                uint32_t bh[4][2], bl[4][2];
#pragma unroll
                for (int jj = 0; jj < 2; ++jj) {
                    if (!jj_act[jj]) continue;
                    const uint32_t nrow =
                        (uint32_t)(wn * 32 + jj * 16 + ((lane >> 4) & 1) * 8 +
                                   (lane & 7));
                    const uint32_t off =
                        nrow * LDR80 + (((lane >> 3) & 1) * 16) + kb;
                    uint32_t t[4];
                    ldsm4(t, sBhi + off);
                    bh[jj * 2][0] = t[0]; bh[jj * 2][1] = t[1];
                    bh[jj * 2 + 1][0] = t[2]; bh[jj * 2 + 1][1] = t[3];
                    ldsm4(t, sBlo + off);
                    bl[jj * 2][0] = t[0]; bl[jj * 2][1] = t[1];
                    bl[jj * 2 + 1][0] = t[2]; bl[jj * 2 + 1][1] = t[3];
                }
#pragma unroll
                for (int mi = 0; mi < 4; ++mi)
#pragma unroll
                    for (int nj = 0; nj < 4; ++nj) {
                        if (!nj_act[nj]) continue;
                        mma16816(acc[mi][nj], ah[mi], bh[nj]);
                        mma16816(acc[mi][nj], ah[mi], bl[nj]);
                        mma16816(acc[mi][nj], al[mi], bh[nj]);
                    }
            }
        }
    }

    // ---- epilogue via swizzled smem (reuses stage area), float4 stores
    __syncthreads();
    float* sC = (float*)smem;   // 64 KB < BIAS1_OFF, bias safe
#pragma unroll
    for (int mi = 0; mi < 4; ++mi) {
        const int rl = wm * 64 + mi * 16 + (lane >> 2);
        const int sw = (rl & 7) << 2;
#pragma unroll
        for (int nj = 0; nj < 4; ++nj) {
            const int cl = wn * 32 + nj * 8 + (lane & 3) * 2;
            const int cs = cl ^ sw;
            sC[rl * 128 + cs]           = acc[mi][nj][0];
            sC[rl * 128 + cs + 1]       = acc[mi][nj][1];
            sC[(rl + 8) * 128 + cs]     = acc[mi][nj][2];
            sC[(rl + 8) * 128 + cs + 1] = acc[mi][nj][3];
        }
    }
    __syncthreads();
#pragma unroll 4
    for (int rr = 0; rr < 16; ++rr) {
        const int row = wid + rr * 8;
        const int col = lane * 4;
        const int swr = (row & 7) << 2;
        float4 v = *(const float4*)&sC[row * 128 + (col ^ swr)];
        float4 bb = *(const float4*)&bias_s[col];
        v.x += bb.x; v.y += bb.y; v.z += bb.z; v.w += bb.w;
        *(float4*)(C + (size_t)(m0 + row) * XGS + n0 + col) = v;
    }
}

// ---------------------------------------------------------------------------
// Pre-converted bf16 GEMM (GEMM2, ldc=513 unaligned).
// Epilogue: swizzled smem stage -> per-lane CONTIGUOUS STG.32 stores
// (col = lane + q*32): every warp store instruction covers 32 consecutive
// floats = 128 B = 4 full sectors (vs 12.5% sector efficiency before).
// ---------------------------------------------------------------------------
#define MAT_BYTES ABF_BYTES
#define STAGE_BYTES (4 * MAT_BYTES)      // 40960
#define SMEM_BIAS (2 * STAGE_BYTES)
#define SMEM_TOTAL (SMEM_BIAS + 512)     // 82432

__global__ __launch_bounds__(256, 2) void gemm_bf16_nt(
    const __nv_bfloat16* __restrict__ Ahi, const __nv_bfloat16* __restrict__ Alo,
    const __nv_bfloat16* __restrict__ Bhi, const __nv_bfloat16* __restrict__ Blo,
    const float* __restrict__ bias, float* __restrict__ C,
    int ldc, int Nreal, int Kp, int nKC)
{
    extern __shared__ __align__(16) char smem[];
    const uint32_t sbase = smem_u32(smem);
    float* bias_s = (float*)(smem + SMEM_BIAS);

    const int tid  = threadIdx.x;
    const int lane = tid & 31;
    const int wid  = tid >> 5;
    const int wm   = wid & 1;
    const int wn   = wid >> 1;

    const int m0 = blockIdx.x * 128;
    const int n0 = blockIdx.y * 128;

    bool nj_act[4], jj_act[2];
#pragma unroll
    for (int nj = 0; nj < 4; ++nj)
        nj_act[nj] = (n0 + wn * 32 + nj * 8) < Nreal;
    jj_act[0] = nj_act[0] | nj_act[1];
    jj_act[1] = nj_act[2] | nj_act[3];
    const bool warp_act = jj_act[0] | jj_act[1];

    float acc[4][4][4];
#pragma unroll
    for (int i = 0; i < 4; ++i)
#pragma unroll
        for (int j = 0; j < 4; ++j)
#pragma unroll
            for (int q = 0; q < 4; ++q) acc[i][j][q] = 0.f;

    auto issue = [&](int kc, int stage) {
        const uint32_t s32 = sbase + stage * STAGE_BYTES;
#pragma unroll
        for (int i = 0; i < 2; ++i) {
            const int chunk = tid + i * 256;
            const int row = chunk >> 2;
            const int g = chunk & 3;
            const uint32_t dofs = row * LDR80 + g * 16;
            const size_t aofs = (size_t)(m0 + row) * Kp + kc * 32 + g * 8;
            const size_t bofs = (size_t)(n0 + row) * Kp + kc * 32 + g * 8;
            cpasync16(s32 + 0 * MAT_BYTES + dofs, Ahi + aofs);
            cpasync16(s32 + 1 * MAT_BYTES + dofs, Alo + aofs);
            cpasync16(s32 + 2 * MAT_BYTES + dofs, Bhi + bofs);
            cpasync16(s32 + 3 * MAT_BYTES + dofs, Blo + bofs);
        }
    };

    issue(0, 0);
    CP_COMMIT();
    if (tid < 128)
        bias_s[tid] = (n0 + tid < Nreal) ? bias[n0 + tid] : 0.f;

    for (int kc = 0; kc < nKC; ++kc) {
        const int cur = kc & 1;
        CP_WAIT0();
        __syncthreads();

        if (kc + 1 < nKC) {
            issue(kc + 1, cur ^ 1);
            CP_COMMIT();
        }

        const uint32_t sAhi = sbase + cur * STAGE_BYTES;
        const uint32_t sAlo = sAhi + MAT_BYTES;
        const uint32_t sBhi = sAhi + 2 * MAT_BYTES;
        const uint32_t sBlo = sAhi + 3 * MAT_BYTES;

        if (warp_act) {
#pragma unroll
            for (int k16 = 0; k16 < 2; ++k16) {
                const uint32_t kb = k16 * 32;
                uint32_t ah[4][4], al[4][4];
#pragma unroll
                for (int mi = 0; mi < 4; ++mi) {
                    const uint32_t off =
                        (uint32_t)(wm * 64 + mi * 16 + (lane & 15)) * LDR80 +
                        ((lane >> 4) * 16) + kb;
                    ldsm4(ah[mi], sAhi + off);
                    ldsm4(al[mi], sAlo + off);
                }
                uint32_t bh[4][2], bl[4][2];
#pragma unroll
                for (int jj = 0; jj < 2; ++jj) {
                    if (!jj_act[jj]) continue;
                    const uint32_t nrow =
                        (uint32_t)(wn * 32 + jj * 16 + ((lane >> 4) & 1) * 8 +
                                   (lane & 7));
                    const uint32_t off =
                        nrow * LDR80 + (((lane >> 3) & 1) * 16) + kb;
                    uint32_t t[4];
                    ldsm4(t, sBhi + off);
                    bh[jj * 2][0] = t[0]; bh[jj * 2][1] = t[1];
                    bh[jj * 2 + 1][0] = t[2]; bh[jj * 2 + 1][1] = t[3];
                    ldsm4(t, sBlo + off);
                    bl[jj * 2][0] = t[0]; bl[jj * 2][1] = t[1];
                    bl[jj * 2 + 1][0] = t[2]; bl[jj * 2 + 1][1] = t[3];
                }
#pragma unroll
                for (int mi = 0; mi < 4; ++mi)
#pragma unroll
                    for (int nj = 0; nj < 4; ++nj) {
                        if (!nj_act[nj]) continue;
                        mma16816(acc[mi][nj], ah[mi], bh[nj]);
                        mma16816(acc[mi][nj], ah[mi], bl[nj]);
                        mma16816(acc[mi][nj], al[mi], bh[nj]);
                    }
            }
        }
    }

    __syncthreads();
    float* sC = (float*)smem;
#pragma unroll
    for (int mi = 0; mi < 4; ++mi) {
        const int rl = wm * 64 + mi * 16 + (lane >> 2);
        const int sw = (rl & 7) << 2;
#pragma unroll
        for (int nj = 0; nj < 4; ++nj) {
            const int cl = wn * 32 + nj * 8 + (lane & 3) * 2;
            const int cs = cl ^ sw;
            sC[rl * 128 + cs]           = acc[mi][nj][0];
            sC[rl * 128 + cs + 1]       = acc[mi][nj][1];
            sC[(rl + 8) * 128 + cs]     = acc[mi][nj][2];
            sC[(rl + 8) * 128 + cs + 1] = acc[mi][nj][3];
        }
    }
    __syncthreads();

    // coalesced scalar stores: col = lane + q*32 (32 consecutive floats/instr)
#pragma unroll 4
    for (int rr = 0; rr < 16; ++rr) {
        const int row = wid + rr * 8;
        const int swr = (row & 7) << 2;
        float* dstrow = C + (size_t)(m0 + row) * ldc + n0;
#pragma unroll
        for (int q = 0; q < 4; ++q) {
            const int col = lane + q * 32;
            float v = sC[row * 128 + (col ^ swr)] + bias_s[col];
            if (n0 + col < Nreal) dstrow[col] = v;
        }
    }
}

// ---------------------------------------------------------------------------
// Column-512 GEMV: out[m, 512] = sum_k hs[m,k] * W_out[512,k] + b_out[512]
// ---------------------------------------------------------------------------
__global__ __launch_bounds__(256) void gemv_col512(
    const float* __restrict__ W_out, const float* __restrict__ b_out,
    float* __restrict__ out)
{
    const int gw = (blockIdx.x * 256 + threadIdx.x) >> 5;
    const int lane = threadIdx.x & 31;
    if (gw >= MROWS) return;

    const uint32_t hw = ((const uint32_t*)(g_hshi + (size_t)gw * KP2))[lane];
    const uint32_t lw = ((const uint32_t*)(g_hslo + (size_t)gw * KP2))[lane];
    __nv_bfloat162 h2 = *(const __nv_bfloat162*)&hw;
    __nv_bfloat162 l2 = *(const __nv_bfloat162*)&lw;
    const int k = lane * 2;
    float h0 = __bfloat162float(h2.x) + __bfloat162float(l2.x);
    float h1 = __bfloat162float(h2.y) + __bfloat162float(l2.y);
    float w0 = (k < HH) ? W_out[512 * HH + k] : 0.f;
    float w1 = (k + 1 < HH) ? W_out[512 * HH + k + 1] : 0.f;
    float s = h0 * w0 + h1 * w1;
#pragma unroll
    for (int o = 16; o > 0; o >>= 1)
        s += __shfl_down_sync(0xFFFFFFFFu, s, o);
    if (lane == 0) out[(size_t)gw * FF + 512] = s + b_out[512];
}

// ---------------------------------------------------------------------------
// LSTM scan over batch axis. One block per t (grid 512, 256 threads).
//   threads 0..223: unit u = j>>2, gate g = j&3. Scalar FMA dot (R12 form),
//     per-gate PARALLEL activation, then lane 4u gathers via __shfl_sync and
//     does the cell update into double-buffered h_s. ONE barrier per step.
//   warp 7: store crew — writes step b-1's h as bf16 hi/lo.
// xg prefetched 2 steps deep.
// ---------------------------------------------------------------------------
__global__ __launch_bounds__(256) void lstm_scan(
    const float* __restrict__ W_hh, const float* __restrict__ b_hh)
{
    __shared__ __align__(16) float h_s[2][56];

    const int t = blockIdx.x;
    const int j = threadIdx.x;
    const int lane = j & 31;
    const int wid = j >> 5;

    const int u = j >> 2;                  // 0..55 for dot threads
    const int g = j & 3;
    const bool dotth = (j < 224);          // warps 0..6
    const bool actth = dotth && (g == 0) && (u < HH);
    const int row = dotth ? (g * HH + ((u < HH) ? u : HH - 1)) : 0;

    float w[HH];
    float bj = 0.f;
    if (dotth) {
#pragma unroll
        for (int k = 0; k < HH; ++k) w[k] = W_hh[row * HH + k];
        bj = b_hh[row];
    }
    float c = 0.f;
    if (j < 56) { h_s[0][j] = 0.f; h_s[1][j] = 0.f; }

    // 2-deep xg prefetch (xg column index == row)
    float pre0 = 0.f, pre1 = 0.f;
    if (dotth && u < HH) {
        pre0 = g_xg[(size_t)t * XGS + row];
        pre1 = g_xg[((size_t)TT + t) * XGS + row];
    }
    __syncthreads();

    for (int b = 0; b < BB; ++b) {
        const int cur = b & 1;
        if (dotth) {
            float g0 = pre0 + bj;
            pre0 = pre1;
            if (b + 2 < BB && u < HH)
                pre1 = g_xg[((size_t)(b + 2) * TT + t) * XGS + row];
            float g1 = 0.f, g2 = 0.f, g3 = 0.f;
#pragma unroll
            for (int k = 0; k < 48; k += 4) {
                float4 hv = *(const float4*)&h_s[cur][k];
                g0 += w[k + 0] * hv.x;
                g1 += w[k + 1] * hv.y;
                g2 += w[k + 2] * hv.z;
                g3 += w[k + 3] * hv.w;
            }
            g0 += w[48] * h_s[cur][48];
            g1 += w[49] * h_s[cur][49];
            float gd = (g0 + g1) + (g2 + g3);

            // per-gate activation IN PARALLEL (g=2 is the tanh gate)
            float act = (g == 2) ? tanh_fast(gd) : sigm_fast(gd);

            // gather unit's activated gates into lane 4u
            float sf = __shfl_sync(0xFFFFFFFFu, act, (lane & ~3) | 1);
            float tg = __shfl_sync(0xFFFFFFFFu, act, (lane & ~3) | 2);
            float so = __shfl_sync(0xFFFFFFFFu, act, (lane & ~3) | 3);
            if (actth) {
                c = sf * c + act * tg;       // act == si on g==0 lanes
                h_s[cur ^ 1][u] = so * tanh_fast(c);
            }
        } else if (wid == 7 && b > 0) {
            // store h of step b-1 (in h_s[cur]) as bf16 hi/lo
            const size_t o = ((size_t)(b - 1) * TT + t) * KP2;
#pragma unroll
            for (int s = 0; s < 2; ++s) {
                const int slot = lane + s * 32;
                float hv = (slot < HH) ? h_s[cur][slot] : 0.f;
                __nv_bfloat16 hh = __float2bfloat16(hv);
                g_hshi[o + slot] = hh;
                g_hslo[o + slot] = __float2bfloat16(hv - __bfloat162float(hh));
            }
        }
        __syncthreads();
    }

    // final step's h lives in h_s[BB & 1] = h_s[0]
    if (wid == 7) {
        const size_t o = ((size_t)(BB - 1) * TT + t) * KP2;
#pragma unroll
        for (int s = 0; s < 2; ++s) {
            const int slot = lane + s * 32;
            float hv = (slot < HH) ? h_s[0][slot] : 0.f;
            __nv_bfloat16 hh = __float2bfloat16(hv);
            g_hshi[o + slot] = hh;
            g_hslo[o + slot] = __float2bfloat16(hv - __bfloat162float(hh));
        }
    }
}

// ---------------------------------------------------------------------------
extern "C" void kernel_launch(void* const* d_in, const int* in_sizes, int n_in,
                              void* d_out, int out_size)
{
    const float* x     = (const float*)d_in[0];
    const float* W_ih  = (const float*)d_in[1];
    const float* W_hh  = (const float*)d_in[2];
    const float* b_ih  = (const float*)d_in[3];
    const float* b_hh  = (const float*)d_in[4];
    const float* W_out = (const float*)d_in[5];
    const float* b_out = (const float*)d_in[6];
    float* out = (float*)d_out;

    float* xg = nullptr;
    __nv_bfloat16 *wihhi, *wihlo, *hshi, *hslo, *wohi, *wolo;
    cudaGetSymbolAddress((void**)&xg, g_xg);
    cudaGetSymbolAddress((void**)&wihhi, g_wihhi);
    cudaGetSymbolAddress((void**)&wihlo, g_wihlo);
    cudaGetSymbolAddress((void**)&hshi, g_hshi);
    cudaGetSymbolAddress((void**)&hslo, g_hslo);
    cudaGetSymbolAddress((void**)&wohi, g_wohi);
    cudaGetSymbolAddress((void**)&wolo, g_wolo);

    cudaFuncSetAttribute(gemm1_fused,
                         cudaFuncAttributeMaxDynamicSharedMemorySize,
                         SMEM1_TOTAL);
    cudaFuncSetAttribute(gemm_bf16_nt,
                         cudaFuncAttributeMaxDynamicSharedMemorySize,
                         SMEM_TOTAL);

    // 0) weight conversions only (tiny)
    conv_w<<<NB_WIH + NB_WO, 256>>>(W_ih, W_out);

    // 1) xg = x @ W_ih^T + b_ih — fused fp32->bf16 conversion in-kernel
    {
        dim3 grid(NP1 / 128, MROWS / 128);   // (2, 256) n-fastest
        gemm1_fused<<<grid, 256, SMEM1_TOTAL>>>(x, wihhi, wihlo, b_ih, xg);
    }
    // 2) LSTM scan (writes hs as bf16 hi/lo)
    lstm_scan<<<TT, 256>>>(W_hh, b_hh);

    // 3) out[:, 0:512] = hs @ W_out[0:512]^T + b_out
    {
        dim3 grid(MROWS / 128, NP2 / 128);   // (256, 4)
        gemm_bf16_nt<<<grid, 256, SMEM_TOTAL>>>(hshi, hslo, wohi, wolo,
                                                b_out, out, FF, NP2, KP2, NKC2);
    }
    // 3b) out[:, 512] via warp-per-row GEMV
    gemv_col512<<<MROWS / 8, 256>>>(W_out, b_out, out);
}

// round 15
// speedup vs baseline: 1.4507x; 1.4507x over previous
#include <cuda_runtime.h>
#include <cuda_fp16.h>
#include <math.h>
#include <stdint.h>

// Problem constants (fixed by the reference)
#define BB 64
#define TT 512
#define FF 513
#define HH 50
#define G4 200          // 4*H
#define MROWS (BB*TT)   // 32768

#define KP1 544         // K=513 padded to 17*32
#define NKC1 17
#define KP2 64          // K=50 padded to 2*32
#define NKC2 2
#define NP1 256         // W_ih rows padded
#define NP2 512         // W_out rows 0..511 (col 512 via gemv)
#define XGS 256         // xg row stride (padded for aligned float4 stores)

// Scratch (static device globals — no allocation in kernel_launch)
__device__ float g_xg[MROWS * XGS];
__device__ __half g_wih16[NP1 * KP1];
__device__ __half g_hs16[MROWS * KP2];
__device__ __half g_wo16[NP2 * KP2];

// ===========================================================================
// PTX helpers
// ===========================================================================
__device__ __forceinline__ uint32_t smem_u32(const void* p) {
    uint32_t a;
    asm("{ .reg .u64 t; cvta.to.shared.u64 t, %1; cvt.u32.u64 %0, t; }"
        : "=r"(a) : "l"(p));
    return a;
}
__device__ __forceinline__ void ldsm4(uint32_t* r, uint32_t a) {
    asm volatile("ldmatrix.sync.aligned.m8n8.x4.shared.b16 {%0,%1,%2,%3}, [%4];"
                 : "=r"(r[0]), "=r"(r[1]), "=r"(r[2]), "=r"(r[3]) : "r"(a));
}
__device__ __forceinline__ void mma16816h(float* c, const uint32_t* a,
                                          const uint32_t* b) {
    asm volatile(
        "mma.sync.aligned.m16n8k16.row.col.f32.f16.f16.f32 "
        "{%0,%1,%2,%3}, {%4,%5,%6,%7}, {%8,%9}, {%0,%1,%2,%3};"
        : "+f"(c[0]), "+f"(c[1]), "+f"(c[2]), "+f"(c[3])
        : "r"(a[0]), "r"(a[1]), "r"(a[2]), "r"(a[3]), "r"(b[0]), "r"(b[1]));
}
__device__ __forceinline__ void cpasync16(uint32_t dst, const void* src) {
    asm volatile("cp.async.cg.shared.global [%0], [%1], 16;"
                 :: "r"(dst), "l"(src));
}
__device__ __forceinline__ void cpasync4_zfill(uint32_t dst, const void* src,
                                               int srcsz) {
    asm volatile("cp.async.ca.shared.global [%0], [%1], 4, %2;"
                 :: "r"(dst), "l"(src), "r"(srcsz));
}
#define CP_COMMIT() asm volatile("cp.async.commit_group;" ::: "memory")
#define CP_WAIT0()  asm volatile("cp.async.wait_group 0;" ::: "memory")

// fast activations: single MUFU.EX2-based, clamped; rel err ~1e-6
__device__ __forceinline__ float sigm_fast(float x) {
    x = fminf(fmaxf(x, -30.f), 30.f);
    return __fdividef(1.f, 1.f + __expf(-x));
}
__device__ __forceinline__ float tanh_fast(float x) {
    x = fminf(fmaxf(x, -15.f), 15.f);
    float e = __expf(-2.f * x);
    return __fdividef(1.f - e, 1.f + e);
}

// ===========================================================================
// Weight conversion: fp32 -> zero-padded fp16 (W_ih, W_out only).
// ===========================================================================
#define NB_WIH ((NP1 * (KP1/8) + 255) / 256)        // 68
#define NB_WO  ((NP2 * (KP2/8) + 255) / 256)        // 16

__device__ __forceinline__ void conv_body_h(
    const float* __restrict__ src, __half* __restrict__ dst,
    int srcR, int srcC, int dstR, int dstC, int idx)
{
    int gpr = dstC >> 3;
    if (idx >= dstR * gpr) return;
    int r = idx / gpr;
    int c0 = (idx - r * gpr) * 8;
    __half hv[8];
#pragma unroll
    for (int i = 0; i < 8; ++i) {
        int c = c0 + i;
        float v = (r < srcR && c < srcC) ? __ldg(&src[(size_t)r * srcC + c]) : 0.f;
        hv[i] = __float2half_rn(v);
    }
    *(uint4*)&dst[(size_t)r * dstC + c0] = *(uint4*)hv;
}

__global__ void conv_w(const float* __restrict__ wih,
                       const float* __restrict__ wo)
{
    int gb = blockIdx.x;
    if (gb < NB_WIH)
        conv_body_h(wih, g_wih16, G4, FF, NP1, KP1, gb * 256 + threadIdx.x);
    else
        conv_body_h(wo, g_wo16, FF, HH, NP2, KP2,
                    (gb - NB_WIH) * 256 + threadIdx.x);
}

// ===========================================================================
// Shared GEMM building blocks
// ===========================================================================
#define LDR80 80
#define ABF_BYTES 10240                  // 128 rows x 80 B (fp16 tile)

// ---------------------------------------------------------------------------
// FUSED GEMM1: xg[m, 0:200] = x[m,:] @ W_ih^T + b_ih, fp32 x converted
// to fp16 IN-KERNEL (smem staging). Single-product fp16 MMA. KC=32.
// Grid (2, 256): n-tile fastest -> A re-read hits L2.
// ---------------------------------------------------------------------------
#define RAW_OFF   0
#define RAW_ROWB  144                    // 32 fp32 (128 B) + 16 B pad
#define RAW_BYTES (128 * RAW_ROWB)       // 18432
#define CONVA_OFF RAW_BYTES              // 18432
#define CONVA_ST  ABF_BYTES              // 10240 per stage
#define B1_OFF    (CONVA_OFF + 2 * CONVA_ST)   // 38912
#define B1_ST     ABF_BYTES
#define BIAS1_OFF (B1_OFF + 2 * B1_ST)   // 59392
#define SMEM1_TOTAL (BIAS1_OFF + 512)    // 59904

__global__ __launch_bounds__(256, 2) void gemm1_fused(
    const float* __restrict__ x,
    const __half* __restrict__ Bm,
    const float* __restrict__ bias, float* __restrict__ C)
{
    extern __shared__ __align__(16) char smem[];
    const uint32_t sbase = smem_u32(smem);
    float* bias_s = (float*)(smem + BIAS1_OFF);

    const int tid  = threadIdx.x;
    const int lane = tid & 31;
    const int wid  = tid >> 5;
    const int wm   = wid & 1;
    const int wn   = wid >> 1;

    const int n0 = blockIdx.x * 128;   // n fastest
    const int m0 = blockIdx.y * 128;

    bool nj_act[4], jj_act[2];
#pragma unroll
    for (int nj = 0; nj < 4; ++nj)
        nj_act[nj] = (n0 + wn * 32 + nj * 8) < G4;
    jj_act[0] = nj_act[0] | nj_act[1];
    jj_act[1] = nj_act[2] | nj_act[3];
    const bool warp_act = jj_act[0] | jj_act[1];

    float acc[4][4][4];
#pragma unroll
    for (int i = 0; i < 4; ++i)
#pragma unroll
        for (int j = 0; j < 4; ++j)
#pragma unroll
            for (int q = 0; q < 4; ++q) acc[i][j][q] = 0.f;

    // raw fp32 A chunk: 128 x 32 fp32, 4-byte zfill cp.async (row stride 513)
    auto issueA = [&](int kc) {
#pragma unroll
        for (int i = 0; i < 16; ++i) {
            const int w = tid + i * 256;       // 0..4095
            const int row = w >> 5;
            const int col = w & 31;
            const int gc = kc * 32 + col;
            const uint32_t dst = sbase + RAW_OFF + row * RAW_ROWB + col * 4;
            const float* src = x + (size_t)(m0 + row) * FF + gc;
            cpasync4_zfill(dst, src, (gc < FF) ? 4 : 0);
        }
    };
    // B chunk (pre-converted fp16, Kp1 stride)
    auto issueB = [&](int kc, int stage) {
        const uint32_t s32 = sbase + B1_OFF + stage * B1_ST;
#pragma unroll
        for (int i = 0; i < 2; ++i) {
            const int chunk = tid + i * 256;   // 0..511
            const int row = chunk >> 2;
            const int g = chunk & 3;
            const uint32_t dofs = row * LDR80 + g * 16;
            const size_t bofs = (size_t)(n0 + row) * KP1 + kc * 32 + g * 8;
            cpasync16(s32 + dofs, Bm + bofs);
        }
    };

    issueA(0);
    issueB(0, 0);
    CP_COMMIT();
    if (tid < 128)
        bias_s[tid] = (n0 + tid < G4) ? bias[n0 + tid] : 0.f;

    const int crow  = tid >> 1;
    const int chalf = (tid & 1) << 4;   // 0 or 16

    for (int kc = 0; kc < NKC1; ++kc) {
        const int cur = kc & 1;
        CP_WAIT0();
        __syncthreads();   // raw A kc + B kc ready; prior compute done

        // ---- convert raw fp32 -> fp16 into conv stage `cur`
        {
            const float4* rp =
                (const float4*)(smem + RAW_OFF + crow * RAW_ROWB + chalf * 4);
            float f[16];
#pragma unroll
            for (int i = 0; i < 4; ++i)
                *(float4*)&f[i * 4] = rp[i];
            __half hv[16];
#pragma unroll
            for (int i = 0; i < 16; ++i)
                hv[i] = __float2half_rn(f[i]);
            char* hd = smem + CONVA_OFF + cur * CONVA_ST + crow * LDR80 + chalf * 2;
            *(uint4*)hd        = ((uint4*)hv)[0];
            *(uint4*)(hd + 16) = ((uint4*)hv)[1];
        }
        __syncthreads();   // conversions visible; raw buffer free

        if (kc + 1 < NKC1) {
            issueA(kc + 1);
            issueB(kc + 1, cur ^ 1);
            CP_COMMIT();
        }

        const uint32_t sA = sbase + CONVA_OFF + cur * CONVA_ST;
        const uint32_t sB = sbase + B1_OFF + cur * B1_ST;

        if (warp_act) {
#pragma unroll
            for (int k16 = 0; k16 < 2; ++k16) {
                const uint32_t kb = k16 * 32;
                uint32_t a[4][4];
#pragma unroll
                for (int mi = 0; mi < 4; ++mi) {
                    const uint32_t off =
                        (uint32_t)(wm * 64 + mi * 16 + (lane & 15)) * LDR80 +
                        ((lane >> 4) * 16) + kb;
                    ldsm4(a[mi], sA + off);
                }
                uint32_t b[4][2];
#pragma unroll
                for (int jj = 0; jj < 2; ++jj) {
                    if (!jj_act[jj]) continue;
                    const uint32_t nrow =
                        (uint32_t)(wn * 32 + jj * 16 + ((lane >> 4) & 1) * 8 +
                                   (lane & 7));
                    const uint32_t off =
                        nrow * LDR80 + (((lane >> 3) & 1) * 16) + kb;
                    uint32_t t[4];
                    ldsm4(t, sB + off);
                    b[jj * 2][0] = t[0]; b[jj * 2][1] = t[1];
                    b[jj * 2 + 1][0] = t[2]; b[jj * 2 + 1][1] = t[3];
                }
#pragma unroll
                for (int mi = 0; mi < 4; ++mi)
#pragma unroll
                    for (int nj = 0; nj < 4; ++nj) {
                        if (!nj_act[nj]) continue;
                        mma16816h(acc[mi][nj], a[mi], b[nj]);
                    }
            }
        }
    }

    // ---- epilogue via swizzled smem (reuses stage area), float4 stores
    __syncthreads();
    float* sC = (float*)smem;   // 64 KB... BIAS1_OFF=59392 < 65536! stage area
    // NOTE: sC needs 64 KB but smem is only 59904. Re-stage in two halves.
    // Half 0: rows 0..63 ; Half 1: rows 64..127. (56 KB usable below bias? no)
    // Use 32-row slabs: 32*128*4 = 16384 bytes — fits easily below BIAS1_OFF.
#pragma unroll
    for (int slab = 0; slab < 4; ++slab) {
        // each slab covers rows [slab*32, slab*32+32)
        // fragment rows rl = wm*64 + mi*16 + (lane>>2) and rl+8
#pragma unroll
        for (int mi = 0; mi < 4; ++mi) {
            const int rl = wm * 64 + mi * 16 + (lane >> 2);
#pragma unroll
            for (int half = 0; half < 2; ++half) {
                const int rr = rl + half * 8;
                if ((rr >> 5) != slab) continue;
                const int lr = rr & 31;
                const int sw = (rr & 7) << 2;
#pragma unroll
                for (int nj = 0; nj < 4; ++nj) {
                    const int cl = wn * 32 + nj * 8 + (lane & 3) * 2;
                    const int cs = cl ^ sw;
                    sC[lr * 128 + cs]     = acc[mi][nj][half * 2];
                    sC[lr * 128 + cs + 1] = acc[mi][nj][half * 2 + 1];
                }
            }
        }
        __syncthreads();
        // 8 warps x 4 rows each: warp handles rows wid*4..wid*4+3 of slab
#pragma unroll
        for (int r4 = 0; r4 < 4; ++r4) {
            const int lr = wid * 4 + r4;
            const int row = slab * 32 + lr;
            const int swr = (row & 7) << 2;
            const int col = lane * 4;
            float4 v = *(const float4*)&sC[lr * 128 + (col ^ swr)];
            float4 bb = *(const float4*)&bias_s[col];
            v.x += bb.x; v.y += bb.y; v.z += bb.z; v.w += bb.w;
            *(float4*)(C + (size_t)(m0 + row) * XGS + n0 + col) = v;
        }
        __syncthreads();
    }
}

// ---------------------------------------------------------------------------
// Pre-converted fp16 GEMM (GEMM2, ldc=513). Single-product fp16 MMA.
// ---------------------------------------------------------------------------
#define STAGE2 (2 * ABF_BYTES)           // A | B = 20480
#define SMEM2_BIAS (2 * STAGE2)          // 40960
#define SMEM2_TOTAL (SMEM2_BIAS + 512 + 128 * 128 * 4)  // + sC 64KB = 106 KB? no
// sC overlaps stages after mainloop; need max(40960+512, 65536+512)... too big
// for 2 CTAs. Use slab epilogue like gemm1: sC slab = 16 KB, overlaps stages.
#define SMEM2_SZ (SMEM2_BIAS + 512)      // 41472

__global__ __launch_bounds__(256, 2) void gemm_fp16_nt(
    const __half* __restrict__ Am, const __half* __restrict__ Bm,
    const float* __restrict__ bias, float* __restrict__ C,
    int ldc, int Nreal, int Kp, int nKC)
{
    extern __shared__ __align__(16) char smem[];
    const uint32_t sbase = smem_u32(smem);
    float* bias_s = (float*)(smem + SMEM2_BIAS);

    const int tid  = threadIdx.x;
    const int lane = tid & 31;
    const int wid  = tid >> 5;
    const int wm   = wid & 1;
    const int wn   = wid >> 1;

    const int m0 = blockIdx.x * 128;
    const int n0 = blockIdx.y * 128;

    bool nj_act[4], jj_act[2];
#pragma unroll
    for (int nj = 0; nj < 4; ++nj)
        nj_act[nj] = (n0 + wn * 32 + nj * 8) < Nreal;
    jj_act[0] = nj_act[0] | nj_act[1];
    jj_act[1] = nj_act[2] | nj_act[3];
    const bool warp_act = jj_act[0] | jj_act[1];

    float acc[4][4][4];
#pragma unroll
    for (int i = 0; i < 4; ++i)
#pragma unroll
        for (int j = 0; j < 4; ++j)
#pragma unroll
            for (int q = 0; q < 4; ++q) acc[i][j][q] = 0.f;

    auto issue = [&](int kc, int stage) {
        const uint32_t s32 = sbase + stage * STAGE2;
#pragma unroll
        for (int i = 0; i < 2; ++i) {
            const int chunk = tid + i * 256;
            const int row = chunk >> 2;
            const int g = chunk & 3;
            const uint32_t dofs = row * LDR80 + g * 16;
            const size_t aofs = (size_t)(m0 + row) * Kp + kc * 32 + g * 8;
            const size_t bofs = (size_t)(n0 + row) * Kp + kc * 32 + g * 8;
            cpasync16(s32 + dofs, Am + aofs);
            cpasync16(s32 + ABF_BYTES + dofs, Bm + bofs);
        }
    };

    issue(0, 0);
    CP_COMMIT();
    if (tid < 128)
        bias_s[tid] = (n0 + tid < Nreal) ? bias[n0 + tid] : 0.f;

    for (int kc = 0; kc < nKC; ++kc) {
        const int cur = kc & 1;
        CP_WAIT0();
        __syncthreads();

        if (kc + 1 < nKC) {
            issue(kc + 1, cur ^ 1);
            CP_COMMIT();
        }

        const uint32_t sA = sbase + cur * STAGE2;
        const uint32_t sB = sA + ABF_BYTES;

        if (warp_act) {
#pragma unroll
            for (int k16 = 0; k16 < 2; ++k16) {
                const uint32_t kb = k16 * 32;
                uint32_t a[4][4];
#pragma unroll
                for (int mi = 0; mi < 4; ++mi) {
                    const uint32_t off =
                        (uint32_t)(wm * 64 + mi * 16 + (lane & 15)) * LDR80 +
                        ((lane >> 4) * 16) + kb;
                    ldsm4(a[mi], sA + off);
                }
                uint32_t b[4][2];
#pragma unroll
                for (int jj = 0; jj < 2; ++jj) {
                    if (!jj_act[jj]) continue;
                    const uint32_t nrow =
                        (uint32_t)(wn * 32 + jj * 16 + ((lane >> 4) & 1) * 8 +
                                   (lane & 7));
                    const uint32_t off =
                        nrow * LDR80 + (((lane >> 3) & 1) * 16) + kb;
                    uint32_t t[4];
                    ldsm4(t, sB + off);
                    b[jj * 2][0] = t[0]; b[jj * 2][1] = t[1];
                    b[jj * 2 + 1][0] = t[2]; b[jj * 2 + 1][1] = t[3];
                }
#pragma unroll
                for (int mi = 0; mi < 4; ++mi)
#pragma unroll
                    for (int nj = 0; nj < 4; ++nj) {
                        if (!nj_act[nj]) continue;
                        mma16816h(acc[mi][nj], a[mi], b[nj]);
                    }
            }
        }
    }

    // ---- slab epilogue (32-row slabs through 16 KB of smem)
    __syncthreads();
    float* sC = (float*)smem;
#pragma unroll
    for (int slab = 0; slab < 4; ++slab) {
#pragma unroll
        for (int mi = 0; mi < 4; ++mi) {
            const int rl = wm * 64 + mi * 16 + (lane >> 2);
#pragma unroll
            for (int half = 0; half < 2; ++half) {
                const int rr = rl + half * 8;
                if ((rr >> 5) != slab) continue;
                const int lr = rr & 31;
                const int sw = (rr & 7) << 2;
#pragma unroll
                for (int nj = 0; nj < 4; ++nj) {
                    const int cl = wn * 32 + nj * 8 + (lane & 3) * 2;
                    const int cs = cl ^ sw;
                    sC[lr * 128 + cs]     = acc[mi][nj][half * 2];
                    sC[lr * 128 + cs + 1] = acc[mi][nj][half * 2 + 1];
                }
            }
        }
        __syncthreads();
#pragma unroll
        for (int r4 = 0; r4 < 4; ++r4) {
            const int lr = wid * 4 + r4;
            const int row = slab * 32 + lr;
            const int swr = (row & 7) << 2;
            float* dstrow = C + (size_t)(m0 + row) * ldc + n0;
#pragma unroll
            for (int q = 0; q < 4; ++q) {
                const int col = lane + q * 32;
                float v = sC[lr * 128 + (col ^ swr)] + bias_s[col];
                if (n0 + col < Nreal) dstrow[col] = v;
            }
        }
        __syncthreads();
    }
}

// ---------------------------------------------------------------------------
// Column-512 GEMV: out[m, 512] = sum_k hs[m,k] * W_out[512,k] + b_out[512]
// ---------------------------------------------------------------------------
__global__ __launch_bounds__(256) void gemv_col512(
    const float* __restrict__ W_out, const float* __restrict__ b_out,
    float* __restrict__ out)
{
    const int gw = (blockIdx.x * 256 + threadIdx.x) >> 5;
    const int lane = threadIdx.x & 31;
    if (gw >= MROWS) return;

    const __half2 h2 = ((const __half2*)(g_hs16 + (size_t)gw * KP2))[lane];
    const int k = lane * 2;
    float h0 = __half2float(__low2half(h2));
    float h1 = __half2float(__high2half(h2));
    float w0 = (k < HH) ? W_out[512 * HH + k] : 0.f;
    float w1 = (k + 1 < HH) ? W_out[512 * HH + k + 1] : 0.f;
    float s = h0 * w0 + h1 * w1;
#pragma unroll
    for (int o = 16; o > 0; o >>= 1)
        s += __shfl_down_sync(0xFFFFFFFFu, s, o);
    if (lane == 0) out[(size_t)gw * FF + 512] = s + b_out[512];
}

// ---------------------------------------------------------------------------
// LSTM scan over batch axis. One block per t (grid 512, 256 threads).
// R12 structure: one barrier/step, parallel per-gate activations,
// warp-7 store crew (now fp16 single), 2-deep xg prefetch.
// ---------------------------------------------------------------------------
__global__ __launch_bounds__(256) void lstm_scan(
    const float* __restrict__ W_hh, const float* __restrict__ b_hh)
{
    __shared__ __align__(16) float h_s[2][56];

    const int t = blockIdx.x;
    const int j = threadIdx.x;
    const int lane = j & 31;
    const int wid = j >> 5;

    const int u = j >> 2;
    const int g = j & 3;
    const bool dotth = (j < 224);
    const bool actth = dotth && (g == 0) && (u < HH);
    const int row = dotth ? (g * HH + ((u < HH) ? u : HH - 1)) : 0;

    float w[HH];
    float bj = 0.f;
    if (dotth) {
#pragma unroll
        for (int k = 0; k < HH; ++k) w[k] = W_hh[row * HH + k];
        bj = b_hh[row];
    }
    float c = 0.f;
    if (j < 56) { h_s[0][j] = 0.f; h_s[1][j] = 0.f; }

    float pre0 = 0.f, pre1 = 0.f;
    if (dotth && u < HH) {
        pre0 = g_xg[(size_t)t * XGS + row];
        pre1 = g_xg[((size_t)TT + t) * XGS + row];
    }
    __syncthreads();

    for (int b = 0; b < BB; ++b) {
        const int cur = b & 1;
        if (dotth) {
            float g0 = pre0 + bj;
            pre0 = pre1;
            if (b + 2 < BB && u < HH)
                pre1 = g_xg[((size_t)(b + 2) * TT + t) * XGS + row];
            float g1 = 0.f, g2 = 0.f, g3 = 0.f;
#pragma unroll
            for (int k = 0; k < 48; k += 4) {
                float4 hv = *(const float4*)&h_s[cur][k];
                g0 += w[k + 0] * hv.x;
                g1 += w[k + 1] * hv.y;
                g2 += w[k + 2] * hv.z;
                g3 += w[k + 3] * hv.w;
            }
            g0 += w[48] * h_s[cur][48];
            g1 += w[49] * h_s[cur][49];
            float gd = (g0 + g1) + (g2 + g3);

            float act = (g == 2) ? tanh_fast(gd) : sigm_fast(gd);

            float sf = __shfl_sync(0xFFFFFFFFu, act, (lane & ~3) | 1);
            float tg = __shfl_sync(0xFFFFFFFFu, act, (lane & ~3) | 2);
            float so = __shfl_sync(0xFFFFFFFFu, act, (lane & ~3) | 3);
            if (actth) {
                c = sf * c + act * tg;
                h_s[cur ^ 1][u] = so * tanh_fast(c);
            }
        } else if (wid == 7 && b > 0) {
            const size_t o = ((size_t)(b - 1) * TT + t) * KP2;
#pragma unroll
            for (int s = 0; s < 2; ++s) {
                const int slot = lane + s * 32;
                float hv = (slot < HH) ? h_s[cur][slot] : 0.f;
                g_hs16[o + slot] = __float2half_rn(hv);
            }
        }
        __syncthreads();
    }

    if (wid == 7) {
        const size_t o = ((size_t)(BB - 1) * TT + t) * KP2;
#pragma unroll
        for (int s = 0; s < 2; ++s) {
            const int slot = lane + s * 32;
            float hv = (slot < HH) ? h_s[0][slot] : 0.f;
            g_hs16[o + slot] = __float2half_rn(hv);
        }
    }
}

// ---------------------------------------------------------------------------
extern "C" void kernel_launch(void* const* d_in, const int* in_sizes, int n_in,
                              void* d_out, int out_size)
{
    const float* x     = (const float*)d_in[0];
    const float* W_ih  = (const float*)d_in[1];
    const float* W_hh  = (const float*)d_in[2];
    const float* b_ih  = (const float*)d_in[3];
    const float* b_hh  = (const float*)d_in[4];
    const float* W_out = (const float*)d_in[5];
    const float* b_out = (const float*)d_in[6];
    float* out = (float*)d_out;

    float* xg = nullptr;
    __half *wih16, *hs16, *wo16;
    cudaGetSymbolAddress((void**)&xg, g_xg);
    cudaGetSymbolAddress((void**)&wih16, g_wih16);
    cudaGetSymbolAddress((void**)&hs16, g_hs16);
    cudaGetSymbolAddress((void**)&wo16, g_wo16);

    cudaFuncSetAttribute(gemm1_fused,
                         cudaFuncAttributeMaxDynamicSharedMemorySize,
                         SMEM1_TOTAL);
    cudaFuncSetAttribute(gemm_fp16_nt,
                         cudaFuncAttributeMaxDynamicSharedMemorySize,
                         SMEM2_SZ);

    // 0) weight conversions (tiny)
    conv_w<<<NB_WIH + NB_WO, 256>>>(W_ih, W_out);

    // 1) xg = x @ W_ih^T + b_ih — fused fp32->fp16 conversion in-kernel
    {
        dim3 grid(NP1 / 128, MROWS / 128);   // (2, 256) n-fastest
        gemm1_fused<<<grid, 256, SMEM1_TOTAL>>>(x, wih16, b_ih, xg);
    }
    // 2) LSTM scan (writes hs as fp16)
    lstm_scan<<<TT, 256>>>(W_hh, b_hh);

    // 3) out[:, 0:512] = hs @ W_out[0:512]^T + b_out
    {
        dim3 grid(MROWS / 128, NP2 / 128);   // (256, 4)
        gemm_fp16_nt<<<grid, 256, SMEM2_SZ>>>(hs16, wo16, b_out, out,
                                              FF, NP2, KP2, NKC2);
    }
    // 3b) out[:, 512] via warp-per-row GEMV
    gemv_col512<<<MROWS / 8, 256>>>(W_out, b_out, out);
}